// round 15
// baseline (speedup 1.0000x reference)
#include <cuda_runtime.h>
#include <cuda_fp16.h>
#include <math.h>

#define SQ   4096
#define DD   512
#define VV   32000
#define HH   50
#define GHX  150
#define GHXP 160
#define EMBD 10
#define XIN  (DD + VV)

#define NBD  128
#define VPB  250
#define VPBP 256
#define WFBP 264
#define NFB  151      // 150 fb rows + Z row

#define ECL  16       // encoder CTAs per stage (cluster size)
#define EROWS 96      // gate rows per encoder CTA

// ---------------- device scratch ----------------
__device__ float g_h0seq[(size_t)SQ * DD];
__device__ float g_gi1seq[(size_t)SQ * 3 * DD];
__device__ __align__(16) float g_h1x[2][DD];
__device__ float g_dense_gi[GHX];
__device__ __align__(16) float g_acc3[3][NFB * 32];

struct __align__(128) PadCtr { unsigned int v; unsigned int pad[31]; };
__device__ PadCtr g_cnt0, g_cnt1, g_cntD16[16];

__device__ __forceinline__ float sigm(float x) { return 1.f / (1.f + __expf(-x)); }

__device__ __forceinline__ void p_arrive(unsigned int* c) {
    asm volatile("red.release.gpu.add.u32 [%0], %1;" :: "l"(c), "r"(1u) : "memory");
}
__device__ __forceinline__ void p_wait_ge(unsigned int* p, unsigned int tgt) {
    unsigned int v;
    do { asm volatile("ld.acquire.gpu.u32 %0, [%1];" : "=r"(v) : "l"(p) : "memory"); }
    while ((int)(v - tgt) < 0);
}
#define CLUSTER_SYNC() do { \
    asm volatile("barrier.cluster.arrive.aligned;" ::: "memory"); \
    asm volatile("barrier.cluster.wait.aligned;" ::: "memory"); } while (0)

__device__ __forceinline__ float dot8h(uint4 a, uint4 b) {
    const __half2* pa = (const __half2*)&a;
    const __half2* pb = (const __half2*)&b;
    float acc = 0.f;
    #pragma unroll
    for (int i = 0; i < 4; i++) {
        float2 x = __half22float2(pa[i]);
        float2 y = __half22float2(pb[i]);
        acc += x.x * y.x + x.y * y.y;
    }
    return acc;
}

// conflict-free half matvec partial, 96-row chunked layout (stride 96 uint4).
__device__ __forceinline__ float mv_cf96(const uint4* W4, const uint4* h4,
                                         int r, int hh) {
    const uint4* wp = W4 + (hh << 5) * EROWS + r;
    float acc = 0.f;
    #pragma unroll
    for (int jo = 0; jo < 8; jo++) {
        __half2 ha = __floats2half2_rn(0.f, 0.f);
        #pragma unroll
        for (int ji = 0; ji < 4; ji++) {
            int j = (jo << 2) + ji;
            uint4 wv = wp[j * EROWS];
            uint4 hv = h4[(hh << 5) + j];
            const __half2* a2 = (const __half2*)&wv;
            const __half2* b2 = (const __half2*)&hv;
            ha = __hfma2(a2[0], b2[0], ha);
            ha = __hfma2(a2[1], b2[1], ha);
            ha = __hfma2(a2[2], b2[2], ha);
            ha = __hfma2(a2[3], b2[3], ha);
        }
        float2 f = __half22float2(ha);
        acc += f.x + f.y;
    }
    acc += __shfl_xor_sync(0xffffffffu, acc, 16);
    return acc;
}

// ---------------- init ----------------
__global__ void k_init() {
    int t = blockIdx.x * blockDim.x + threadIdx.x;
    if (t == 0) { g_cnt0.v = 0u; g_cnt1.v = 0u; }
    if (t < 16) g_cntD16[t].v = 0u;
    if (t < 3 * NFB * 32)
        ((float*)g_acc3)[t] = (t == GHX * 32) ? 1.f : 0.f;
}

// ---------------- encoder: 3 pipelined clusters of 16 CTAs (R12 exact) -------
__global__ void __launch_bounds__(256, 1) __cluster_dims__(ECL, 1, 1)
k_encoder(
    const int*   __restrict__ input_mol, const float* __restrict__ emb,
    const float* __restrict__ eWih0, const float* __restrict__ eWhh0,
    const float* __restrict__ ebih0, const float* __restrict__ ebhh0,
    const float* __restrict__ eWih1, const float* __restrict__ eWhh1,
    const float* __restrict__ ebih1, const float* __restrict__ ebhh1)
{
    extern __shared__ unsigned char smraw[];
    __half*  WtH  = (__half*)smraw;                       // 96*512 chunked
    float*   fp   = (float*)(smraw + EROWS * 512 * 2);
    float*   dots = fp;  fp += EROWS;
    float*   g96  = fp;  fp += EROWS;
    float*   wih0 = fp;  fp += EROWS * EMBD;
    float*   bA   = fp;  fp += EROWS;
    float*   bB   = fp;  fp += EROWS;
    float*   xs   = fp;  fp += 16;
    __half2* hh2  = (__half2*)fp;                         // 256 half2

    const int tid  = threadIdx.x;
    const int role = blockIdx.x >> 4;
    const int ci   = blockIdx.x & 15;
    const int bd   = 256;
    const int w = tid >> 5, l = tid & 31;
    const uint4* h4 = (const uint4*)hh2;
    const uint4* W4 = (const uint4*)WtH;

    const float* Wsrc = (role == 0) ? eWhh0 : (role == 1) ? eWih1 : eWhh1;
    for (int idx = tid; idx < EROWS * 512; idx += bd) {
        int r = idx >> 9, c = idx & 511;
        int grow = (role == 1) ? (ci * EROWS + r)
                               : ((r >> 5) * DD + ci * 32 + (r & 31));
        WtH[((c >> 3) * EROWS + r) * 8 + (c & 7)] = __float2half(Wsrc[(size_t)grow * DD + c]);
    }
    if (role == 0) {
        for (int idx = tid; idx < EROWS * EMBD; idx += bd) {
            int r = idx / EMBD, c = idx % EMBD;
            int grow = (r >> 5) * DD + ci * 32 + (r & 31);
            wih0[idx] = eWih0[grow * EMBD + c];
        }
        if (tid < EROWS) {
            int grow = (tid >> 5) * DD + ci * 32 + (tid & 31);
            bA[tid] = ebih0[grow];
            bB[tid] = ebhh0[grow];
        }
        if (tid < EMBD) xs[tid] = emb[input_mol[0] * EMBD + tid];
    } else if (role == 1) {
        if (tid < EROWS) bA[tid] = ebih1[ci * EROWS + tid];
    } else {
        if (tid < EROWS) {
            int grow = (tid >> 5) * DD + ci * 32 + (tid & 31);
            bB[tid] = ebhh1[grow];
        }
    }
    if (tid < 256) hh2[tid] = __floats2half2_rn(0.f, 0.f);
    __syncthreads();

    if (role == 0) {
        // ---- layer-0 recurrence ----
        float hreg = 0.f;
        for (int t = 0; t < SQ; t++) {
            if (w < 6) {
                const int ii = l & 15, hh = l >> 4;
                const int r = w * 16 + ii;
                float acc = mv_cf96(W4, h4, r, hh);
                if (hh == 0) dots[r] = acc + bB[r];
            } else if (w == 6) {
                #pragma unroll
                for (int k = 0; k < 3; k++) {
                    int r = l * 3 + k;
                    float gi = bA[r];
                    #pragma unroll
                    for (int c = 0; c < EMBD; c++) gi += wih0[r * EMBD + c] * xs[c];
                    g96[r] = gi;
                }
            }
            __syncthreads();
            float xn = 0.f;
            if (t + 1 < SQ && tid < EMBD) xn = emb[input_mol[t + 1] * EMBD + tid];
            if (tid < 32) {
                float r = sigm(g96[tid] + dots[tid]);
                float z = sigm(g96[32 + tid] + dots[32 + tid]);
                float n = tanhf(g96[64 + tid] + r * dots[64 + tid]);
                float h = (1.f - z) * n + z * hreg;
                hreg = h;
                __stcg(&g_h0seq[(size_t)t * DD + ci * 32 + tid], h);
            }
            __syncthreads();
            if (tid == 0) p_arrive(&g_cnt0.v);
            if (tid < EMBD) xs[tid] = xn;
            CLUSTER_SYNC();
            if (tid < 128) {
                float4 v = __ldcg((const float4*)(g_h0seq + (size_t)t * DD) + tid);
                hh2[tid * 2]     = __floats2half2_rn(v.x, v.y);
                hh2[tid * 2 + 1] = __floats2half2_rn(v.z, v.w);
            }
            __syncthreads();
        }
    } else if (role == 1) {
        // ---- gi1 = Wih1*h0 + b ----
        for (int t = 0; t < SQ; t++) {
            if (tid == 224) p_wait_ge(&g_cnt0.v, (unsigned)ECL * (unsigned)(t + 1));
            __syncthreads();
            if (tid < 128) {
                float4 v = __ldcg((const float4*)(g_h0seq + (size_t)t * DD) + tid);
                hh2[tid * 2]     = __floats2half2_rn(v.x, v.y);
                hh2[tid * 2 + 1] = __floats2half2_rn(v.z, v.w);
            }
            __syncthreads();
            if (w < 6) {
                const int ii = l & 15, hh = l >> 4;
                const int r = w * 16 + ii;
                float acc = mv_cf96(W4, h4, r, hh);
                if (hh == 0)
                    __stcg(&g_gi1seq[(size_t)t * (3 * DD) + ci * EROWS + r], acc + bA[r]);
            }
            __syncthreads();
            if (tid == 0) p_arrive(&g_cnt1.v);
        }
    } else {
        // ---- layer-1 recurrence ----
        float hreg = 0.f;
        for (int t = 0; t < SQ; t++) {
            if (w == 6) {
                if (l == 0) p_wait_ge(&g_cnt1.v, (unsigned)ECL * (unsigned)(t + 1));
                __syncwarp(0xffffffffu);
                #pragma unroll
                for (int k = 0; k < 3; k++) {
                    int r = l * 3 + k;
                    int grow = (r >> 5) * DD + ci * 32 + (r & 31);
                    g96[r] = __ldcg(&g_gi1seq[(size_t)t * (3 * DD) + grow]);
                }
            } else if (w < 6) {
                const int ii = l & 15, hh = l >> 4;
                const int r = w * 16 + ii;
                float acc = mv_cf96(W4, h4, r, hh);
                if (hh == 0) dots[r] = acc + bB[r];
            }
            __syncthreads();
            if (tid < 32) {
                float r = sigm(g96[tid] + dots[tid]);
                float z = sigm(g96[32 + tid] + dots[32 + tid]);
                float n = tanhf(g96[64 + tid] + r * dots[64 + tid]);
                float h = (1.f - z) * n + z * hreg;
                hreg = h;
                __stcg(&g_h1x[t & 1][ci * 32 + tid], h);
            }
            CLUSTER_SYNC();
            if (tid < 128) {
                float4 v = __ldcg((const float4*)(g_h1x[t & 1]) + tid);
                hh2[tid * 2]     = __floats2half2_rn(v.x, v.y);
                hh2[tid * 2 + 1] = __floats2half2_rn(v.z, v.w);
            }
            __syncthreads();
        }
    }
}

// ---------------- mid ----------------
__global__ void k_mid(const float* __restrict__ dWih1, const float* __restrict__ dbih1) {
    const float* dense = g_h1x[1];
    int w = threadIdx.x >> 5, lane = threadIdx.x & 31;
    for (int g = w; g < GHX; g += 16) {
        const float* row = dWih1 + (size_t)g * XIN;
        float acc = 0.f;
        for (int c = lane; c < DD; c += 32) acc += row[c] * dense[c];
        #pragma unroll
        for (int o = 16; o; o >>= 1) acc += __shfl_xor_sync(0xffffffffu, acc, o);
        if (lane == 0) g_dense_gi[g] = dbih1[g] + acc;
    }
}

// ---------------- decoder: R12 + 16 replica slots + gi2 pair-split -----------
__global__ void __launch_bounds__(512, 1) k_decoder(
    const float* __restrict__ dWih1,
    const float* __restrict__ dWhh1, const float* __restrict__ dWih2,
    const float* __restrict__ dWhh2,
    const float* __restrict__ dbhh1, const float* __restrict__ dbih2,
    const float* __restrict__ dbhh2,
    const float* __restrict__ W2, const float* __restrict__ b2,
    float* __restrict__ out)
{
    extern __shared__ unsigned char smraw[];
    __half* WfbH = (__half*)smraw;
    __half* W2tH = WfbH + NFB * WFBP;
    __half* esh  = W2tH + HH * VPBP;
    float*  fp   = (float*)(esh + VPBP);
    float*  tW1  = fp;  fp += HH * GHXP;
    float*  tW2i = fp;  fp += HH * GHXP;
    float*  tW2h = fp;  fp += HH * GHXP;
    float*  sgi  = fp;  fp += GHX;
    float*  sb1  = fp;  fp += GHX;
    float*  sb2i = fp;  fp += GHX;
    float*  sb2h = fp;  fp += GHX;
    float*  gh1s = fp;  fp += GHX;
    float*  gh2s = fp;  fp += GHX;
    float*  gi2s = fp;  fp += GHX;
    float*  ugf  = fp;  fp += 152;
    float*  h1s  = fp;  fp += 64;
    float*  h2os = fp;  fp += 64;

    const int b = blockIdx.x, tid = threadIdx.x;
    const int j0 = b * VPB;
    const int slot = b & 15;                 // 16 replica slots -> 8 writers/address
    const int w = tid >> 5;
    const int lane = tid & 31;
    const int jcol = tid >> 1, hpar = tid & 1;
    const int sub = lane >> 3, kk = lane & 7;

    for (int idx = tid; idx < NFB * WFBP; idx += 512) {
        int r = idx / WFBP, c = idx % WFBP;
        float v = 0.f;
        if (c < VPB) v = (r < GHX) ? dWih1[(size_t)r * XIN + DD + j0 + c] : 1.f;
        WfbH[idx] = __float2half(v);
    }
    for (int idx = tid; idx < HH * VPBP; idx += 512) {
        int c = idx >> 8, j = idx & 255;
        W2tH[idx] = __float2half((j < VPB) ? W2[(size_t)(j0 + j) * HH + c] : 0.f);
    }
    for (int idx = tid; idx < HH * GHX; idx += 512) {
        int g = idx / HH, c = idx % HH;
        tW1 [c * GHXP + g] = dWhh1[idx];
        tW2i[c * GHXP + g] = dWih2[idx];
        tW2h[c * GHXP + g] = dWhh2[idx];
    }
    if (tid < GHX) {
        sgi[tid] = g_dense_gi[tid];
        sb1[tid] = dbhh1[tid]; sb2i[tid] = dbih2[tid]; sb2h[tid] = dbhh2[tid];
    }
    if (tid < 64) { h1s[tid] = 0.f; h2os[tid] = 0.f; }
    if (tid >= VPB && tid < VPBP) esh[tid] = __float2half(0.f);
    const float b2r = (!hpar && jcol < VPB) ? b2[j0 + jcol] : 0.f;
    __syncthreads();

    float eprev = 0.f;

    for (int t = 0; t < SQ; t++) {
        // phase 1: hoisted gh matvecs concurrent with counter polling
        if (tid < GHX) {
            float a = sb1[tid];
            #pragma unroll
            for (int c = 0; c < HH; c++) a += tW1[c * GHXP + tid] * h1s[c];
            gh1s[tid] = a;
        } else if (tid >= 256 && tid < 256 + GHX) {
            int r = tid - 256;
            float a = sb2h[r];
            #pragma unroll
            for (int c = 0; c < HH; c++) a += tW2h[c * GHXP + r] * h2os[c];
            gh2s[r] = a;
        } else if (tid >= 416 && tid < 432 && t > 0) {
            p_wait_ge(&g_cntD16[tid - 416].v, 8u * (unsigned)t);
        }
        __syncthreads();
        // phase 2: stage ugf (sum 16 replicas = one 128B line); zero next buffer
        {
            float* bufR = g_acc3[t % 3];
            float* bufZ = g_acc3[(t + 2) % 3];
            if (tid < NFB) {
                __stcg(&bufZ[tid * 32 + slot], 0.f);
                const float4* lr = (const float4*)(bufR + tid * 32);
                float4 a0 = __ldcg(lr), a1 = __ldcg(lr + 1);
                float4 a2 = __ldcg(lr + 2), a3 = __ldcg(lr + 3);
                ugf[tid] = (((a0.x + a0.y) + (a0.z + a0.w)) + ((a1.x + a1.y) + (a1.z + a1.w)))
                         + (((a2.x + a2.y) + (a2.z + a2.w)) + ((a3.x + a3.y) + (a3.z + a3.w)));
            }
        }
        __syncthreads();
        const float rz = 1.f / ugf[GHX];

        // phase 3: h1 update
        if (tid < HH) {
            float gr = sgi[tid]          + ugf[tid] * rz          + gh1s[tid];
            float gz = sgi[HH + tid]     + ugf[HH + tid] * rz     + gh1s[HH + tid];
            float gn = sgi[2 * HH + tid] + ugf[2 * HH + tid] * rz;
            float r = sigm(gr), z = sigm(gz);
            float n = tanhf(gn + r * gh1s[2 * HH + tid]);
            h1s[tid] = (1.f - z) * n + z * h1s[tid];
        }
        __syncthreads();
        // phase 4: gi2 pair-split (2 threads per row, 25-term halves)
        if (tid < 320) {
            int row = tid >> 1, p = tid & 1;
            int rowc = (row < GHX) ? row : (GHX - 1);
            float a = 0.f;
            const int c0 = p * 25;
            #pragma unroll
            for (int c = 0; c < 25; c++) a += tW2i[(c0 + c) * GHXP + rowc] * h1s[c0 + c];
            a += __shfl_xor_sync(0xffffffffu, a, 1);
            if (!p && row < GHX) gi2s[row] = a + sb2i[row];
        }
        __syncthreads();
        // phase 5: h2 update
        if (tid < HH) {
            float r = sigm(gi2s[tid] + gh2s[tid]);
            float z = sigm(gi2s[HH + tid] + gh2s[HH + tid]);
            float n = tanhf(gi2s[2 * HH + tid] + r * gh2s[2 * HH + tid]);
            h2os[tid] = (1.f - z) * n + z * h2os[tid];
        }
        __syncthreads();

        // phase 6: logits + exp (pair-split)
        float acc = b2r;
        {
            const int c0 = hpar * 25;
            #pragma unroll
            for (int c = 0; c < 25; c++)
                acc += h2os[c0 + c] * __half2float(W2tH[(c0 + c) * VPBP + jcol]);
        }
        acc += __shfl_xor_sync(0xffffffffu, acc, 1);
        float e = __expf(acc);
        if (!hpar && jcol < VPB) esh[jcol] = __float2half(e);
        __syncthreads();

        // phase 7: fb matvec (rotated rows) + atomics
        float* accW = g_acc3[(t + 1) % 3];
        const uint4* es4 = (const uint4*)esh;
        uint4 ev0 = es4[kk], ev1 = es4[kk + 8], ev2 = es4[kk + 16], ev3 = es4[kk + 24];
        #pragma unroll
        for (int p = 0; p < 3; p++) {
            int vrow = p * 64 + w * 4 + sub;
            int rowc = (vrow < NFB) ? vrow : (NFB - 1);
            int row = rowc + b; if (row >= NFB) row -= NFB;
            const uint4* wr = (const uint4*)(WfbH + row * WFBP);
            float a = dot8h(wr[kk], ev0) + dot8h(wr[kk + 8], ev1)
                    + dot8h(wr[kk + 16], ev2) + dot8h(wr[kk + 24], ev3);
            a += __shfl_xor_sync(0xffffffffu, a, 1);
            a += __shfl_xor_sync(0xffffffffu, a, 2);
            a += __shfl_xor_sync(0xffffffffu, a, 4);
            if (kk == 0 && vrow < NFB) atomicAdd(&accW[row * 32 + slot], a);
        }
        __syncthreads();
        if (tid == 0) p_arrive(&g_cntD16[b & 15].v);

        if (t > 0 && !hpar && jcol < VPB)
            __stcs(&out[(size_t)(t - 1) * VV + j0 + jcol], eprev * rz);
        eprev = e;
    }

    // epilogue
    if (tid < 16) p_wait_ge(&g_cntD16[tid].v, 8u * (unsigned)SQ);
    __syncthreads();
    if (tid == 0) {
        const float* zr = g_acc3[SQ % 3] + GHX * 32;
        float z = 0.f;
        #pragma unroll
        for (int i = 0; i < 16; i++) z += __ldcg(zr + i);
        ugf[0] = 1.f / z;
    }
    __syncthreads();
    if (!hpar && jcol < VPB)
        __stcs(&out[(size_t)(SQ - 1) * VV + j0 + jcol], eprev * ugf[0]);
}

// ---------------- launcher ----------------
extern "C" void kernel_launch(void* const* d_in, const int* in_sizes, int n_in,
                              void* d_out, int out_size) {
    const int*   input_mol = (const int*)  d_in[0];
    const float* emb   = (const float*)d_in[1];
    const float* eWih0 = (const float*)d_in[2];
    const float* eWhh0 = (const float*)d_in[3];
    const float* ebih0 = (const float*)d_in[4];
    const float* ebhh0 = (const float*)d_in[5];
    const float* eWih1 = (const float*)d_in[6];
    const float* eWhh1 = (const float*)d_in[7];
    const float* ebih1 = (const float*)d_in[8];
    const float* ebhh1 = (const float*)d_in[9];
    const float* dWih1 = (const float*)d_in[10];
    const float* dWhh1 = (const float*)d_in[11];
    const float* dbih1 = (const float*)d_in[12];
    const float* dbhh1 = (const float*)d_in[13];
    const float* dWih2 = (const float*)d_in[14];
    const float* dWhh2 = (const float*)d_in[15];
    const float* dbih2 = (const float*)d_in[16];
    const float* dbhh2 = (const float*)d_in[17];
    const float* W2    = (const float*)d_in[18];
    const float* b2    = (const float*)d_in[19];
    float* out = (float*)d_out;

    const size_t esmem = (size_t)EROWS * 512 * 2
                       + (size_t)(2 * EROWS + EROWS * EMBD + 2 * EROWS + 16) * sizeof(float)
                       + 256 * sizeof(__half2);
    const size_t dsmem = (size_t)(NFB * WFBP + HH * VPBP + VPBP) * sizeof(__half)
                       + (size_t)(3 * HH * GHXP + 7 * GHX + 152 + 2 * 64) * sizeof(float);

    cudaFuncSetAttribute(k_encoder, cudaFuncAttributeMaxDynamicSharedMemorySize, (int)esmem);
    cudaFuncSetAttribute(k_encoder, cudaFuncAttributeNonPortableClusterSizeAllowed, 1);
    cudaFuncSetAttribute(k_decoder, cudaFuncAttributeMaxDynamicSharedMemorySize, (int)dsmem);

    k_init<<<(3 * NFB * 32 + 255) / 256, 256>>>();
    k_encoder<<<3 * ECL, 256, esmem>>>(input_mol, emb, eWih0, eWhh0, ebih0, ebhh0,
                                       eWih1, eWhh1, ebih1, ebhh1);
    k_mid<<<1, 512>>>(dWih1, dbih1);
    k_decoder<<<NBD, 512, dsmem>>>(dWih1, dWhh1, dWih2, dWhh2,
                                   dbhh1, dbih2, dbhh2, W2, b2, out);
}

// round 16
// speedup vs baseline: 1.1729x; 1.1729x over previous
#include <cuda_runtime.h>
#include <cuda_fp16.h>
#include <math.h>

#define SQ   4096
#define DD   512
#define VV   32000
#define HH   50
#define GHX  150
#define GHXP 160
#define EMBD 10
#define XIN  (DD + VV)

#define NBD  128
#define VPB  250
#define VPBP 256
#define WFBP 264
#define NFB  151      // 150 fb rows + Z row

#define ECL  16       // encoder CTAs per stage (cluster size)
#define EROWS 96      // gate rows per encoder CTA

// ---------------- device scratch ----------------
__device__ float g_h0seq[(size_t)SQ * DD];
__device__ float g_gi1seq[(size_t)SQ * 3 * DD];
__device__ __align__(16) float g_h1x[2][DD];
__device__ float g_dense_gi[GHX];
__device__ __align__(16) float g_acc3[3][NFB * 32];

struct __align__(128) PadCtr { unsigned int v; unsigned int pad[31]; };
__device__ PadCtr g_cnt0, g_cnt1, g_cntD16[16];

__device__ __forceinline__ float sigm(float x) { return 1.f / (1.f + __expf(-x)); }

__device__ __forceinline__ void p_arrive(unsigned int* c) {
    asm volatile("red.release.gpu.add.u32 [%0], %1;" :: "l"(c), "r"(1u) : "memory");
}
__device__ __forceinline__ void p_wait_ge(unsigned int* p, unsigned int tgt) {
    unsigned int v;
    do { asm volatile("ld.acquire.gpu.u32 %0, [%1];" : "=r"(v) : "l"(p) : "memory"); }
    while ((int)(v - tgt) < 0);
}
#define CLUSTER_SYNC() do { \
    asm volatile("barrier.cluster.arrive.aligned;" ::: "memory"); \
    asm volatile("barrier.cluster.wait.aligned;" ::: "memory"); } while (0)

__device__ __forceinline__ float dot8h(uint4 a, uint4 b) {
    const __half2* pa = (const __half2*)&a;
    const __half2* pb = (const __half2*)&b;
    float acc = 0.f;
    #pragma unroll
    for (int i = 0; i < 4; i++) {
        float2 x = __half22float2(pa[i]);
        float2 y = __half22float2(pb[i]);
        acc += x.x * y.x + x.y * y.y;
    }
    return acc;
}

// conflict-free half matvec partial, 96-row chunked layout (stride 96 uint4).
__device__ __forceinline__ float mv_cf96(const uint4* W4, const uint4* h4,
                                         int r, int hh) {
    const uint4* wp = W4 + (hh << 5) * EROWS + r;
    float acc = 0.f;
    #pragma unroll
    for (int jo = 0; jo < 8; jo++) {
        __half2 ha = __floats2half2_rn(0.f, 0.f);
        #pragma unroll
        for (int ji = 0; ji < 4; ji++) {
            int j = (jo << 2) + ji;
            uint4 wv = wp[j * EROWS];
            uint4 hv = h4[(hh << 5) + j];
            const __half2* a2 = (const __half2*)&wv;
            const __half2* b2 = (const __half2*)&hv;
            ha = __hfma2(a2[0], b2[0], ha);
            ha = __hfma2(a2[1], b2[1], ha);
            ha = __hfma2(a2[2], b2[2], ha);
            ha = __hfma2(a2[3], b2[3], ha);
        }
        float2 f = __half22float2(ha);
        acc += f.x + f.y;
    }
    acc += __shfl_xor_sync(0xffffffffu, acc, 16);
    return acc;
}

// ---------------- init ----------------
__global__ void k_init() {
    int t = blockIdx.x * blockDim.x + threadIdx.x;
    if (t == 0) { g_cnt0.v = 0u; g_cnt1.v = 0u; }
    if (t < 16) g_cntD16[t].v = 0u;
    if (t < 3 * NFB * 32)
        ((float*)g_acc3)[t] = (t == GHX * 32) ? 1.f : 0.f;
}

// ---------------- encoder: 3 pipelined clusters of 16 CTAs (R12 exact) -------
__global__ void __launch_bounds__(256, 1) __cluster_dims__(ECL, 1, 1)
k_encoder(
    const int*   __restrict__ input_mol, const float* __restrict__ emb,
    const float* __restrict__ eWih0, const float* __restrict__ eWhh0,
    const float* __restrict__ ebih0, const float* __restrict__ ebhh0,
    const float* __restrict__ eWih1, const float* __restrict__ eWhh1,
    const float* __restrict__ ebih1, const float* __restrict__ ebhh1)
{
    extern __shared__ unsigned char smraw[];
    __half*  WtH  = (__half*)smraw;                       // 96*512 chunked
    float*   fp   = (float*)(smraw + EROWS * 512 * 2);
    float*   dots = fp;  fp += EROWS;
    float*   g96  = fp;  fp += EROWS;
    float*   wih0 = fp;  fp += EROWS * EMBD;
    float*   bA   = fp;  fp += EROWS;
    float*   bB   = fp;  fp += EROWS;
    float*   xs   = fp;  fp += 16;
    __half2* hh2  = (__half2*)fp;                         // 256 half2

    const int tid  = threadIdx.x;
    const int role = blockIdx.x >> 4;
    const int ci   = blockIdx.x & 15;
    const int bd   = 256;
    const int w = tid >> 5, l = tid & 31;
    const uint4* h4 = (const uint4*)hh2;
    const uint4* W4 = (const uint4*)WtH;

    const float* Wsrc = (role == 0) ? eWhh0 : (role == 1) ? eWih1 : eWhh1;
    for (int idx = tid; idx < EROWS * 512; idx += bd) {
        int r = idx >> 9, c = idx & 511;
        int grow = (role == 1) ? (ci * EROWS + r)
                               : ((r >> 5) * DD + ci * 32 + (r & 31));
        WtH[((c >> 3) * EROWS + r) * 8 + (c & 7)] = __float2half(Wsrc[(size_t)grow * DD + c]);
    }
    if (role == 0) {
        for (int idx = tid; idx < EROWS * EMBD; idx += bd) {
            int r = idx / EMBD, c = idx % EMBD;
            int grow = (r >> 5) * DD + ci * 32 + (r & 31);
            wih0[idx] = eWih0[grow * EMBD + c];
        }
        if (tid < EROWS) {
            int grow = (tid >> 5) * DD + ci * 32 + (tid & 31);
            bA[tid] = ebih0[grow];
            bB[tid] = ebhh0[grow];
        }
        if (tid < EMBD) xs[tid] = emb[input_mol[0] * EMBD + tid];
    } else if (role == 1) {
        if (tid < EROWS) bA[tid] = ebih1[ci * EROWS + tid];
    } else {
        if (tid < EROWS) {
            int grow = (tid >> 5) * DD + ci * 32 + (tid & 31);
            bB[tid] = ebhh1[grow];
        }
    }
    if (tid < 256) hh2[tid] = __floats2half2_rn(0.f, 0.f);
    __syncthreads();

    if (role == 0) {
        // ---- layer-0 recurrence ----
        float hreg = 0.f;
        for (int t = 0; t < SQ; t++) {
            if (w < 6) {
                const int ii = l & 15, hh = l >> 4;
                const int r = w * 16 + ii;
                float acc = mv_cf96(W4, h4, r, hh);
                if (hh == 0) dots[r] = acc + bB[r];
            } else if (w == 6) {
                #pragma unroll
                for (int k = 0; k < 3; k++) {
                    int r = l * 3 + k;
                    float gi = bA[r];
                    #pragma unroll
                    for (int c = 0; c < EMBD; c++) gi += wih0[r * EMBD + c] * xs[c];
                    g96[r] = gi;
                }
            }
            __syncthreads();
            float xn = 0.f;
            if (t + 1 < SQ && tid < EMBD) xn = emb[input_mol[t + 1] * EMBD + tid];
            if (tid < 32) {
                float r = sigm(g96[tid] + dots[tid]);
                float z = sigm(g96[32 + tid] + dots[32 + tid]);
                float n = tanhf(g96[64 + tid] + r * dots[64 + tid]);
                float h = (1.f - z) * n + z * hreg;
                hreg = h;
                __stcg(&g_h0seq[(size_t)t * DD + ci * 32 + tid], h);
            }
            __syncthreads();
            if (tid == 0) p_arrive(&g_cnt0.v);
            if (tid < EMBD) xs[tid] = xn;
            CLUSTER_SYNC();
            if (tid < 128) {
                float4 v = __ldcg((const float4*)(g_h0seq + (size_t)t * DD) + tid);
                hh2[tid * 2]     = __floats2half2_rn(v.x, v.y);
                hh2[tid * 2 + 1] = __floats2half2_rn(v.z, v.w);
            }
            __syncthreads();
        }
    } else if (role == 1) {
        // ---- gi1 = Wih1*h0 + b ----
        for (int t = 0; t < SQ; t++) {
            if (tid == 224) p_wait_ge(&g_cnt0.v, (unsigned)ECL * (unsigned)(t + 1));
            __syncthreads();
            if (tid < 128) {
                float4 v = __ldcg((const float4*)(g_h0seq + (size_t)t * DD) + tid);
                hh2[tid * 2]     = __floats2half2_rn(v.x, v.y);
                hh2[tid * 2 + 1] = __floats2half2_rn(v.z, v.w);
            }
            __syncthreads();
            if (w < 6) {
                const int ii = l & 15, hh = l >> 4;
                const int r = w * 16 + ii;
                float acc = mv_cf96(W4, h4, r, hh);
                if (hh == 0)
                    __stcg(&g_gi1seq[(size_t)t * (3 * DD) + ci * EROWS + r], acc + bA[r]);
            }
            __syncthreads();
            if (tid == 0) p_arrive(&g_cnt1.v);
        }
    } else {
        // ---- layer-1 recurrence ----
        float hreg = 0.f;
        for (int t = 0; t < SQ; t++) {
            if (w == 6) {
                if (l == 0) p_wait_ge(&g_cnt1.v, (unsigned)ECL * (unsigned)(t + 1));
                __syncwarp(0xffffffffu);
                #pragma unroll
                for (int k = 0; k < 3; k++) {
                    int r = l * 3 + k;
                    int grow = (r >> 5) * DD + ci * 32 + (r & 31);
                    g96[r] = __ldcg(&g_gi1seq[(size_t)t * (3 * DD) + grow]);
                }
            } else if (w < 6) {
                const int ii = l & 15, hh = l >> 4;
                const int r = w * 16 + ii;
                float acc = mv_cf96(W4, h4, r, hh);
                if (hh == 0) dots[r] = acc + bB[r];
            }
            __syncthreads();
            if (tid < 32) {
                float r = sigm(g96[tid] + dots[tid]);
                float z = sigm(g96[32 + tid] + dots[32 + tid]);
                float n = tanhf(g96[64 + tid] + r * dots[64 + tid]);
                float h = (1.f - z) * n + z * hreg;
                hreg = h;
                __stcg(&g_h1x[t & 1][ci * 32 + tid], h);
            }
            CLUSTER_SYNC();
            if (tid < 128) {
                float4 v = __ldcg((const float4*)(g_h1x[t & 1]) + tid);
                hh2[tid * 2]     = __floats2half2_rn(v.x, v.y);
                hh2[tid * 2 + 1] = __floats2half2_rn(v.z, v.w);
            }
            __syncthreads();
        }
    }
}

// ---------------- mid ----------------
__global__ void k_mid(const float* __restrict__ dWih1, const float* __restrict__ dbih1) {
    const float* dense = g_h1x[1];
    int w = threadIdx.x >> 5, lane = threadIdx.x & 31;
    for (int g = w; g < GHX; g += 16) {
        const float* row = dWih1 + (size_t)g * XIN;
        float acc = 0.f;
        for (int c = lane; c < DD; c += 32) acc += row[c] * dense[c];
        #pragma unroll
        for (int o = 16; o; o >>= 1) acc += __shfl_xor_sync(0xffffffffu, acc, o);
        if (lane == 0) g_dense_gi[g] = dbih1[g] + acc;
    }
}

// ---------------- decoder: R12 structure, small recurrent weights in fp16 ----
__global__ void __launch_bounds__(512, 1) k_decoder(
    const float* __restrict__ dWih1,
    const float* __restrict__ dWhh1, const float* __restrict__ dWih2,
    const float* __restrict__ dWhh2,
    const float* __restrict__ dbhh1, const float* __restrict__ dbih2,
    const float* __restrict__ dbhh2,
    const float* __restrict__ W2, const float* __restrict__ b2,
    float* __restrict__ out)
{
    extern __shared__ unsigned char smraw[];
    __half* WfbH = (__half*)smraw;                 // [151][264] (row 150 = ones)
    __half* W2tH = WfbH + NFB * WFBP;              // [50][256]
    __half* esh  = W2tH + HH * VPBP;               // [256]
    __half* tW1  = esh  + VPBP;                    // [50][160] Whh1^T fp16
    __half* tW2i = tW1  + HH * GHXP;               // [50][160] Wih2^T fp16
    __half* tW2h = tW2i + HH * GHXP;               // [50][160] Whh2^T fp16
    float*  fp   = (float*)(tW2h + HH * GHXP);
    float*  sgi  = fp;  fp += GHX;
    float*  sb1  = fp;  fp += GHX;
    float*  sb2i = fp;  fp += GHX;
    float*  sb2h = fp;  fp += GHX;
    float*  gh1s = fp;  fp += GHX;
    float*  gh2s = fp;  fp += GHX;
    float*  gi2s = fp;  fp += GHX;
    float*  ugf  = fp;  fp += 152;
    float*  h1s  = fp;  fp += 64;
    float*  h2os = fp;  fp += 64;

    const int b = blockIdx.x, tid = threadIdx.x;
    const int j0 = b * VPB;
    const int slot = b & 7;
    const int w = tid >> 5;
    const int lane = tid & 31;
    const int jcol = tid >> 1, hpar = tid & 1;
    const int sub = lane >> 3, kk = lane & 7;

    for (int idx = tid; idx < NFB * WFBP; idx += 512) {
        int r = idx / WFBP, c = idx % WFBP;
        float v = 0.f;
        if (c < VPB) v = (r < GHX) ? dWih1[(size_t)r * XIN + DD + j0 + c] : 1.f;
        WfbH[idx] = __float2half(v);
    }
    for (int idx = tid; idx < HH * VPBP; idx += 512) {
        int c = idx >> 8, j = idx & 255;
        W2tH[idx] = __float2half((j < VPB) ? W2[(size_t)(j0 + j) * HH + c] : 0.f);
    }
    for (int idx = tid; idx < HH * GHX; idx += 512) {
        int g = idx / HH, c = idx % HH;
        tW1 [c * GHXP + g] = __float2half(dWhh1[idx]);
        tW2i[c * GHXP + g] = __float2half(dWih2[idx]);
        tW2h[c * GHXP + g] = __float2half(dWhh2[idx]);
    }
    if (tid < GHX) {
        sgi[tid] = g_dense_gi[tid];
        sb1[tid] = dbhh1[tid]; sb2i[tid] = dbih2[tid]; sb2h[tid] = dbhh2[tid];
    }
    if (tid < 64) { h1s[tid] = 0.f; h2os[tid] = 0.f; }
    if (tid >= VPB && tid < VPBP) esh[tid] = __float2half(0.f);
    const float b2r = (!hpar && jcol < VPB) ? b2[j0 + jcol] : 0.f;
    __syncthreads();

    float eprev = 0.f;

    for (int t = 0; t < SQ; t++) {
        // phase 1: hoisted gh matvecs concurrent with counter polling
        if (tid < GHX) {
            float a = sb1[tid];
            #pragma unroll
            for (int c = 0; c < HH; c++) a += __half2float(tW1[c * GHXP + tid]) * h1s[c];
            gh1s[tid] = a;
        } else if (tid >= 256 && tid < 256 + GHX) {
            int r = tid - 256;
            float a = sb2h[r];
            #pragma unroll
            for (int c = 0; c < HH; c++) a += __half2float(tW2h[c * GHXP + r]) * h2os[c];
            gh2s[r] = a;
        } else if (tid >= 416 && tid < 432 && t > 0) {
            p_wait_ge(&g_cntD16[tid - 416].v, 8u * (unsigned)t);
        }
        __syncthreads();
        // phase 2: stage ugf (8 replica slots = one 64B read); zero next buffer
        {
            float* bufR = g_acc3[t % 3];
            float* bufZ = g_acc3[(t + 2) % 3];
            if (tid < NFB) {
                __stcg(&bufZ[tid * 32 + slot], 0.f);
                const float4* lr = (const float4*)(bufR + tid * 32);
                float4 a0 = __ldcg(lr), a1 = __ldcg(lr + 1);
                ugf[tid] = ((a0.x + a0.y) + (a0.z + a0.w)) + ((a1.x + a1.y) + (a1.z + a1.w));
            }
        }
        __syncthreads();
        const float rz = 1.f / ugf[GHX];

        // phase 3: h1 update
        if (tid < HH) {
            float gr = sgi[tid]          + ugf[tid] * rz          + gh1s[tid];
            float gz = sgi[HH + tid]     + ugf[HH + tid] * rz     + gh1s[HH + tid];
            float gn = sgi[2 * HH + tid] + ugf[2 * HH + tid] * rz;
            float r = sigm(gr), z = sigm(gz);
            float n = tanhf(gn + r * gh1s[2 * HH + tid]);
            h1s[tid] = (1.f - z) * n + z * h1s[tid];
        }
        __syncthreads();
        // phase 4: gi2 (full-row, fp16 weights)
        if (tid < GHX) {
            float a = sb2i[tid];
            #pragma unroll
            for (int c = 0; c < HH; c++) a += __half2float(tW2i[c * GHXP + tid]) * h1s[c];
            gi2s[tid] = a;
        }
        __syncthreads();
        // phase 5: h2 update
        if (tid < HH) {
            float r = sigm(gi2s[tid] + gh2s[tid]);
            float z = sigm(gi2s[HH + tid] + gh2s[HH + tid]);
            float n = tanhf(gi2s[2 * HH + tid] + r * gh2s[2 * HH + tid]);
            h2os[tid] = (1.f - z) * n + z * h2os[tid];
        }
        __syncthreads();

        // phase 6: logits + exp (pair-split)
        float acc = b2r;
        {
            const int c0 = hpar * 25;
            #pragma unroll
            for (int c = 0; c < 25; c++)
                acc += h2os[c0 + c] * __half2float(W2tH[(c0 + c) * VPBP + jcol]);
        }
        acc += __shfl_xor_sync(0xffffffffu, acc, 1);
        float e = __expf(acc);
        if (!hpar && jcol < VPB) esh[jcol] = __float2half(e);
        __syncthreads();

        // phase 7: fb matvec (rotated rows) + atomics
        float* accW = g_acc3[(t + 1) % 3];
        const uint4* es4 = (const uint4*)esh;
        uint4 ev0 = es4[kk], ev1 = es4[kk + 8], ev2 = es4[kk + 16], ev3 = es4[kk + 24];
        #pragma unroll
        for (int p = 0; p < 3; p++) {
            int vrow = p * 64 + w * 4 + sub;
            int rowc = (vrow < NFB) ? vrow : (NFB - 1);
            int row = rowc + b; if (row >= NFB) row -= NFB;
            const uint4* wr = (const uint4*)(WfbH + row * WFBP);
            float a = dot8h(wr[kk], ev0) + dot8h(wr[kk + 8], ev1)
                    + dot8h(wr[kk + 16], ev2) + dot8h(wr[kk + 24], ev3);
            a += __shfl_xor_sync(0xffffffffu, a, 1);
            a += __shfl_xor_sync(0xffffffffu, a, 2);
            a += __shfl_xor_sync(0xffffffffu, a, 4);
            if (kk == 0 && vrow < NFB) atomicAdd(&accW[row * 32 + slot], a);
        }
        __syncthreads();
        if (tid == 0) p_arrive(&g_cntD16[b & 15].v);

        if (t > 0 && !hpar && jcol < VPB)
            __stcs(&out[(size_t)(t - 1) * VV + j0 + jcol], eprev * rz);
        eprev = e;
    }

    // epilogue
    if (tid < 16) p_wait_ge(&g_cntD16[tid].v, 8u * (unsigned)SQ);
    __syncthreads();
    if (tid == 0) {
        const float* zr = g_acc3[SQ % 3] + GHX * 32;
        float z = 0.f;
        #pragma unroll
        for (int i = 0; i < 8; i++) z += __ldcg(zr + i);
        ugf[0] = 1.f / z;
    }
    __syncthreads();
    if (!hpar && jcol < VPB)
        __stcs(&out[(size_t)(SQ - 1) * VV + j0 + jcol], eprev * ugf[0]);
}

// ---------------- launcher ----------------
extern "C" void kernel_launch(void* const* d_in, const int* in_sizes, int n_in,
                              void* d_out, int out_size) {
    const int*   input_mol = (const int*)  d_in[0];
    const float* emb   = (const float*)d_in[1];
    const float* eWih0 = (const float*)d_in[2];
    const float* eWhh0 = (const float*)d_in[3];
    const float* ebih0 = (const float*)d_in[4];
    const float* ebhh0 = (const float*)d_in[5];
    const float* eWih1 = (const float*)d_in[6];
    const float* eWhh1 = (const float*)d_in[7];
    const float* ebih1 = (const float*)d_in[8];
    const float* ebhh1 = (const float*)d_in[9];
    const float* dWih1 = (const float*)d_in[10];
    const float* dWhh1 = (const float*)d_in[11];
    const float* dbih1 = (const float*)d_in[12];
    const float* dbhh1 = (const float*)d_in[13];
    const float* dWih2 = (const float*)d_in[14];
    const float* dWhh2 = (const float*)d_in[15];
    const float* dbih2 = (const float*)d_in[16];
    const float* dbhh2 = (const float*)d_in[17];
    const float* W2    = (const float*)d_in[18];
    const float* b2    = (const float*)d_in[19];
    float* out = (float*)d_out;

    const size_t esmem = (size_t)EROWS * 512 * 2
                       + (size_t)(2 * EROWS + EROWS * EMBD + 2 * EROWS + 16) * sizeof(float)
                       + 256 * sizeof(__half2);
    const size_t dsmem = (size_t)(NFB * WFBP + HH * VPBP + VPBP + 3 * HH * GHXP) * sizeof(__half)
                       + (size_t)(7 * GHX + 152 + 2 * 64) * sizeof(float);

    cudaFuncSetAttribute(k_encoder, cudaFuncAttributeMaxDynamicSharedMemorySize, (int)esmem);
    cudaFuncSetAttribute(k_encoder, cudaFuncAttributeNonPortableClusterSizeAllowed, 1);
    cudaFuncSetAttribute(k_decoder, cudaFuncAttributeMaxDynamicSharedMemorySize, (int)dsmem);

    k_init<<<(3 * NFB * 32 + 255) / 256, 256>>>();
    k_encoder<<<3 * ECL, 256, esmem>>>(input_mol, emb, eWih0, eWhh0, ebih0, ebhh0,
                                       eWih1, eWhh1, ebih1, ebhh1);
    k_mid<<<1, 512>>>(dWih1, dbih1);
    k_decoder<<<NBD, 512, dsmem>>>(dWih1, dWhh1, dWih2, dWhh2,
                                   dbhh1, dbih2, dbhh2, W2, b2, out);
}